// round 16
// baseline (speedup 1.0000x reference)
#include <cuda_runtime.h>
#include <cuda_bf16.h>
#include <cstdint>

#define BB 2
#define SEQ 2048
#define NHALF 1024
#define DIM 768
#define HEADS 12
#define HD 64
#define DFF 3072
#define COND 128
#define ADA6 (6 * DIM)

typedef __nv_bfloat16 bf16;

// ---------------- scratch ----------------
__device__ float g_ada[BB * ADA6];
__device__ bf16  g_h  [BB * SEQ * DIM];
__device__ bf16  g_qkv[BB * SEQ * 3 * DIM];
__device__ bf16  g_o  [BB * SEQ * DIM];
__device__ float g_x1 [BB * SEQ * DIM];
__device__ bf16  g_h2 [BB * SEQ * DIM];
__device__ bf16  g_mlp[BB * SEQ * DFF];
// bf16 weight copies [K][N]
__device__ bf16 g_wq[DIM * 3 * DIM];
__device__ bf16 g_wo[DIM * DIM];
__device__ bf16 g_w1[DIM * DFF];
__device__ bf16 g_w2[DFF * DIM];

// ---------------- helpers ----------------
__device__ __forceinline__ unsigned sptr(const void* p) {
    return (unsigned)__cvta_generic_to_shared(p);
}
__device__ __forceinline__ void cpa16(unsigned dst, const void* src) {
    asm volatile("cp.async.cg.shared.global [%0], [%1], 16;" :: "r"(dst), "l"(src));
}
__device__ __forceinline__ void ldsm4(unsigned* r, unsigned addr) {
    asm volatile("ldmatrix.sync.aligned.m8n8.x4.shared.b16 {%0,%1,%2,%3}, [%4];"
                 : "=r"(r[0]), "=r"(r[1]), "=r"(r[2]), "=r"(r[3]) : "r"(addr));
}
__device__ __forceinline__ void ldsm4t(unsigned* r, unsigned addr) {
    asm volatile("ldmatrix.sync.aligned.m8n8.x4.trans.shared.b16 {%0,%1,%2,%3}, [%4];"
                 : "=r"(r[0]), "=r"(r[1]), "=r"(r[2]), "=r"(r[3]) : "r"(addr));
}
__device__ __forceinline__ void mma_bf16(float* c, const unsigned* a, const unsigned* b) {
    asm volatile(
        "mma.sync.aligned.m16n8k16.row.col.f32.bf16.bf16.f32 "
        "{%0,%1,%2,%3}, {%4,%5,%6,%7}, {%8,%9}, {%0,%1,%2,%3};"
        : "+f"(c[0]), "+f"(c[1]), "+f"(c[2]), "+f"(c[3])
        : "r"(a[0]), "r"(a[1]), "r"(a[2]), "r"(a[3]), "r"(b[0]), "r"(b[1]));
}
__device__ __forceinline__ unsigned packbf(float a, float b) {
    __nv_bfloat162 p = __floats2bfloat162_rn(a, b);
    return *(unsigned*)&p;
}
__device__ __forceinline__ float tanh_fast(float x) {
    float y;
    asm("tanh.approx.f32 %0, %1;" : "=f"(y) : "f"(x));
    return y;
}
__device__ __forceinline__ float gelu_tanh(float v) {
    float t = v * v * v;
    return 0.5f * v * (1.f + tanh_fast(0.7978845608028654f * (v + 0.044715f * t)));
}

// ---------------- fused weight convert (all 4 weights, one launch) ----------------
#define NQ_WQ (DIM * 3 * DIM / 4)
#define NQ_WO (DIM * DIM / 4)
#define NQ_W1 (DIM * DFF / 4)
#define NQ_W2 (DFF * DIM / 4)
#define NQ_ALL (NQ_WQ + NQ_WO + NQ_W1 + NQ_W2)

__global__ void cvt_all_kernel(const float4* __restrict__ s0, const float4* __restrict__ s1,
                               const float4* __restrict__ s2, const float4* __restrict__ s3) {
    int i = blockIdx.x * blockDim.x + threadIdx.x;
    int stride = gridDim.x * blockDim.x;
    for (; i < NQ_ALL; i += stride) {
        const float4* src;
        uint2* dst;
        int j = i;
        if (j < NQ_WQ) { src = s0; dst = (uint2*)g_wq; }
        else if ((j -= NQ_WQ) < NQ_WO) { src = s1; dst = (uint2*)g_wo; }
        else if ((j -= NQ_WO) < NQ_W1) { src = s2; dst = (uint2*)g_w1; }
        else { j -= NQ_W1; src = s3; dst = (uint2*)g_w2; }
        float4 v = src[j];
        uint2 o;
        o.x = packbf(v.x, v.y);
        o.y = packbf(v.z, v.w);
        dst[j] = o;
    }
}

// ---------------- ada = c @ ada_w + ada_b ----------------
__global__ void ada_kernel(const float* __restrict__ c,
                           const float* __restrict__ ada_w,
                           const float* __restrict__ ada_b) {
    int j = blockIdx.x * blockDim.x + threadIdx.x;
    if (j >= BB * ADA6) return;
    int b = j / ADA6, col = j % ADA6;
    float acc = ada_b[col];
    #pragma unroll 8
    for (int k = 0; k < COND; k++)
        acc += c[b * COND + k] * ada_w[k * ADA6 + col];
    g_ada[j] = acc;
}

// ---------------- LayerNorm + adaLN modulation (bf16 out) ----------------
__global__ void ln_mod_kernel(const float* __restrict__ src, bf16* __restrict__ dst,
                              const float* __restrict__ lnw,
                              int shift_ofs, int scale_ofs) {
    int row = blockIdx.x;
    int b = row / SEQ;
    const float* xr = src + (size_t)row * DIM;
    float s = 0.f, s2 = 0.f;
    for (int i = threadIdx.x; i < DIM; i += blockDim.x) {
        float v = xr[i];
        s += v; s2 += v * v;
    }
    #pragma unroll
    for (int o = 16; o; o >>= 1) {
        s  += __shfl_xor_sync(0xffffffffu, s,  o);
        s2 += __shfl_xor_sync(0xffffffffu, s2, o);
    }
    __shared__ float red[64];
    int wid = threadIdx.x >> 5, lid = threadIdx.x & 31;
    if (lid == 0) { red[wid] = s; red[32 + wid] = s2; }
    __syncthreads();
    if (threadIdx.x == 0) {
        float a = 0.f, bs = 0.f;
        int nw = blockDim.x >> 5;
        for (int w = 0; w < nw; w++) { a += red[w]; bs += red[32 + w]; }
        red[0] = a; red[32] = bs;
    }
    __syncthreads();
    float mu  = red[0] * (1.0f / DIM);
    float var = red[32] * (1.0f / DIM) - mu * mu;
    float inv = rsqrtf(var + 1e-5f);
    const float* ada = g_ada + b * ADA6;
    for (int i = threadIdx.x; i < DIM; i += blockDim.x) {
        float v = (xr[i] - mu) * inv * lnw[i];
        dst[(size_t)row * DIM + i] =
            __float2bfloat16(v * (1.f + ada[scale_ofs + i]) + ada[shift_ofs + i]);
    }
}

// ---------------- bf16 mma.sync GEMM, k64 stages, templated epilogue/tile-N/stages ----------------
// MODE 1: gate*acc+res (fp32) | 2: gelu(acc+bias)->bf16 | 3: gate*(acc+bias)+res (fp32)
// MODE 4: bf16 raw out.   TN: CTA tile N (128/64).   ST: smem pipeline stages (2/3).
#define A64ST 72                     // A smem row stride (bf16): 144B, conflict-free
#define STG_A (128 * A64ST)          // 9216 elems

template <int MODE, int TN, int ST>
__global__ void __launch_bounds__(256)
gemm_bf16(const bf16* __restrict__ A, const bf16* __restrict__ Bm,
          void* __restrict__ Cv, int N, int K,
          const float* __restrict__ bias,
          const float* __restrict__ res, int gate_ofs) {
    constexpr int NT = TN / 16;       // mma n-tiles per warp
    constexpr int NP = TN / 32;       // ldsm4t per s-step
    constexpr int BITER = TN / 32;    // B loader passes
    constexpr int BCH = TN / 8;       // 16B chunks per B row
    constexpr int STG_Bv = 64 * TN;
    constexpr int STG_Tv = STG_A + STG_Bv;

    extern __shared__ bf16 smem[];
    int tid = threadIdx.x;
    int lane = tid & 31, warp = tid >> 5;
    int warpm = warp >> 1, warpn = warp & 1;
    int g = lane >> 2, tg = lane & 3;
    int m0 = blockIdx.y * 128, n0 = blockIdx.x * TN;

    float acc[2][NT][4] = {};

    int T = K / 64;

    #define LOAD_STAGE64(it, st) do { \
        bf16* sa = smem + (st) * STG_Tv; \
        bf16* sb = sa + STG_A; \
        int kofs = (it) * 64; \
        _Pragma("unroll") \
        for (int i4 = 0; i4 < 4; i4++) { \
            int e = tid + i4 * 256; \
            int row = e >> 3, c = e & 7; \
            cpa16(sptr(sa + row * A64ST + c * 8), \
                  &A[(size_t)(m0 + row) * K + kofs + c * 8]); \
        } \
        _Pragma("unroll") \
        for (int i4 = 0; i4 < BITER; i4++) { \
            int e = tid + i4 * 256; \
            int k = e / BCH, bc2 = e % BCH; \
            cpa16(sptr(sb + k * TN + ((bc2 ^ (k & 7)) * 8)), \
                  &Bm[(size_t)(kofs + k) * N + n0 + bc2 * 8]); \
        } \
        asm volatile("cp.async.commit_group;"); \
    } while (0)

    LOAD_STAGE64(0, 0);
    if (T > 1) LOAD_STAGE64(1, 1);

    for (int it = 0; it < T; it++) {
        if (it + 1 < T) asm volatile("cp.async.wait_group 1;");
        else            asm volatile("cp.async.wait_group 0;");
        __syncthreads();
        // ST=3: after the top barrier, all warps finished compute of it-1, so
        // buffer (it+2)%3 == (it-1)%3 is free. Issue loads BEFORE compute.
        if (ST == 3 && it + 2 < T) {
            int st = (it + 2) % 3;
            LOAD_STAGE64(it + 2, st);
        }

        int buf = (ST == 3) ? (it % 3) : (it & 1);
        const bf16* sa = smem + buf * STG_Tv;
        const bf16* sb = sa + STG_A;

        #pragma unroll
        for (int s = 0; s < 4; s++) {
            unsigned a[2][4], b[NT][2];
            #pragma unroll
            for (int mt = 0; mt < 2; mt++) {
                int row = warpm * 32 + mt * 16 + (lane & 15);
                ldsm4(a[mt], sptr(sa + row * A64ST + s * 16 + (lane >> 4) * 8));
            }
            #pragma unroll
            for (int p = 0; p < NP; p++) {
                int k = s * 16 + (lane & 7) + ((lane >> 3) & 1) * 8;
                int nn = warpn * (TN / 2) + p * 16 + (lane >> 4) * 8;
                unsigned r[4];
                ldsm4t(r, sptr(sb + k * TN + (((nn >> 3) ^ (k & 7)) * 8)));
                b[2 * p][0] = r[0]; b[2 * p][1] = r[1];
                b[2 * p + 1][0] = r[2]; b[2 * p + 1][1] = r[3];
            }
            #pragma unroll
            for (int mt = 0; mt < 2; mt++)
                #pragma unroll
                for (int nt = 0; nt < NT; nt++)
                    mma_bf16(acc[mt][nt], a[mt], b[nt]);
        }
        if (ST == 2) {
            __syncthreads();            // all warps done reading buf before refill
            if (it + 2 < T) LOAD_STAGE64(it + 2, it & 1);
        }
    }

    float* C = (float*)Cv;
    bf16* Cb = (bf16*)Cv;
    #pragma unroll
    for (int mt = 0; mt < 2; mt++) {
        #pragma unroll
        for (int i = 0; i < 2; i++) {
            int row = m0 + warpm * 32 + mt * 16 + g + i * 8;
            int bidx = row >> 11;
            #pragma unroll
            for (int nt = 0; nt < NT; nt++) {
                int col = n0 + warpn * (TN / 2) + nt * 8 + 2 * tg;
                float v0 = acc[mt][nt][i * 2 + 0];
                float v1 = acc[mt][nt][i * 2 + 1];
                if (MODE == 4) {
                    *(__nv_bfloat162*)&Cb[(size_t)row * N + col] = __floats2bfloat162_rn(v0, v1);
                } else if (MODE == 1) {
                    float g0 = g_ada[bidx * ADA6 + gate_ofs + col];
                    float g1 = g_ada[bidx * ADA6 + gate_ofs + col + 1];
                    v0 = g0 * v0 + res[(size_t)row * N + col];
                    v1 = g1 * v1 + res[(size_t)row * N + col + 1];
                    *(float2*)&C[(size_t)row * N + col] = make_float2(v0, v1);
                } else if (MODE == 2) {
                    v0 = gelu_tanh(v0 + bias[col]);
                    v1 = gelu_tanh(v1 + bias[col + 1]);
                    *(__nv_bfloat162*)&Cb[(size_t)row * N + col] = __floats2bfloat162_rn(v0, v1);
                } else if (MODE == 3) {
                    v0 += bias[col]; v1 += bias[col + 1];
                    float g0 = g_ada[bidx * ADA6 + gate_ofs + col];
                    float g1 = g_ada[bidx * ADA6 + gate_ofs + col + 1];
                    v0 = g0 * v0 + res[(size_t)row * N + col];
                    v1 = g1 * v1 + res[(size_t)row * N + col + 1];
                    *(float2*)&C[(size_t)row * N + col] = make_float2(v0, v1);
                }
            }
        }
    }
}

#define SMEM_G128_3 (3 * (STG_A + 64 * 128) * 2)
#define SMEM_G64    (2 * (STG_A + 64 * 64) * 2)

// ---------------- RoPE on bf16 qkv ----------------
__global__ void rope_kernel(const float* __restrict__ cosb, const float* __restrict__ sinb) {
    int idx = blockIdx.x * blockDim.x + threadIdx.x;
    const int total = BB * SEQ * 3 * HEADS * 32;
    if (idx >= total) return;
    int d = idx & 31;
    int h = (idx >> 5) % HEADS;
    int t = (idx / (32 * HEADS)) % 3;
    int pos = (idx / (32 * HEADS * 3)) % SEQ;
    int b = idx / (32 * HEADS * 3 * SEQ);
    int ph = pos & (NHALF - 1);
    float c1 = cosb[ph * HD + d],      s1 = sinb[ph * HD + d];
    float c2 = cosb[ph * HD + d + 32], s2 = sinb[ph * HD + d + 32];
    bf16* base = g_qkv + ((size_t)(b * SEQ + pos) * 3 + t) * DIM + h * HD;
    float v1 = __bfloat162float(base[d]), v2 = __bfloat162float(base[d + 32]);
    base[d]      = __float2bfloat16(v1 * c1 - v2 * s1);
    base[d + 32] = __float2bfloat16(v2 * c2 + v1 * s2);
}

// ---------------- mma flash attention, block-sparse ----------------
#define ATS 72   // smem row stride elems (144B): conflict-free ldsm

__global__ void __launch_bounds__(128) attn_mma() {
    __shared__ bf16 Qs[64 * ATS];
    __shared__ bf16 Ks[2][16 * ATS];
    __shared__ bf16 Vs[2][16 * ATS];
    int tid = threadIdx.x, w = tid >> 5, lane = tid & 31;
    int bx = blockIdx.x, h = blockIdx.y, b = blockIdx.z;
    int qb0 = (bx & 1) ? (60 - 4 * (bx >> 1)) : (124 - 4 * (bx >> 1));
    bool first = qb0 < 64;
    int qb = qb0 + w;
    int g = lane >> 2, tg = lane & 3;
    int frow = lane & 15, fch = (lane >> 4) * 8;

    {
        const bf16* qsrc = g_qkv + ((size_t)(b * SEQ + qb0 * 16) * 3) * DIM + h * HD;
        #pragma unroll
        for (int i = 0; i < 4; i++) {
            int e = tid + i * 128;
            int row = e >> 3, c = e & 7;
            *(uint4*)&Qs[row * ATS + c * 8] =
                *(const uint4*)&qsrc[(size_t)row * 3 * DIM + c * 8];
        }
    }
    __syncthreads();

    unsigned qa[4][4];
    #pragma unroll
    for (int s = 0; s < 4; s++)
        ldsm4(qa[s], sptr(&Qs[(w * 16 + frow) * ATS + s * 16 + fch]));

    int nit = first ? (qb0 + 7) : (qb0 - 60);
    #define KB(i) (first ? ((i) < 4 ? qb0 + (i) : 60 + (i)) : 64 + (i))

    #define ATT_LOAD(kb, bf) do { \
        int row = tid >> 3, c = tid & 7; \
        const bf16* kv = g_qkv + ((size_t)(b * SEQ + (kb) * 16 + row) * 3 + 1) * DIM \
                         + h * HD + c * 8; \
        cpa16(sptr(&Ks[bf][row * ATS + c * 8]), kv); \
        cpa16(sptr(&Vs[bf][row * ATS + c * 8]), kv + DIM); \
        asm volatile("cp.async.commit_group;"); \
    } while (0)

    float m0v = -1e30f, m1v = -1e30f, l0 = 0.f, l1 = 0.f;
    float oa[8][4] = {};

    ATT_LOAD(KB(0), 0);
    for (int it = 0; it < nit; it++) {
        int buf = it & 1;
        if (it + 1 < nit) {
            ATT_LOAD(KB(it + 1), buf ^ 1);
            asm volatile("cp.async.wait_group 1;");
        } else {
            asm volatile("cp.async.wait_group 0;");
        }
        __syncthreads();

        bool act = first ? ((it < 4) ? (it == w) : (it - 4 < qb0 + w))
                         : (it < qb0 - 64 + w + 1);
        if (act) {
            float s0[4] = {0, 0, 0, 0}, s1[4] = {0, 0, 0, 0};
            #pragma unroll
            for (int s = 0; s < 4; s++) {
                unsigned kr[4];
                ldsm4(kr, sptr(&Ks[buf][frow * ATS + s * 16 + fch]));
                unsigned b0[2] = {kr[0], kr[2]}, b1[2] = {kr[1], kr[3]};
                mma_bf16(s0, qa[s], b0);
                mma_bf16(s1, qa[s], b1);
            }
            #pragma unroll
            for (int q = 0; q < 4; q++) { s0[q] *= 0.125f; s1[q] *= 0.125f; }
            float rm0 = fmaxf(fmaxf(s0[0], s0[1]), fmaxf(s1[0], s1[1]));
            float rm1 = fmaxf(fmaxf(s0[2], s0[3]), fmaxf(s1[2], s1[3]));
            rm0 = fmaxf(rm0, __shfl_xor_sync(0xffffffffu, rm0, 1));
            rm0 = fmaxf(rm0, __shfl_xor_sync(0xffffffffu, rm0, 2));
            rm1 = fmaxf(rm1, __shfl_xor_sync(0xffffffffu, rm1, 1));
            rm1 = fmaxf(rm1, __shfl_xor_sync(0xffffffffu, rm1, 2));
            float nm0 = fmaxf(m0v, rm0), nm1 = fmaxf(m1v, rm1);
            float c0 = __expf(m0v - nm0), c1 = __expf(m1v - nm1);
            m0v = nm0; m1v = nm1;
            float p00 = __expf(s0[0] - nm0), p01 = __expf(s0[1] - nm0);
            float p02 = __expf(s1[0] - nm0), p03 = __expf(s1[1] - nm0);
            float p10 = __expf(s0[2] - nm1), p11 = __expf(s0[3] - nm1);
            float p12 = __expf(s1[2] - nm1), p13 = __expf(s1[3] - nm1);
            float ls0 = p00 + p01 + p02 + p03;
            float ls1 = p10 + p11 + p12 + p13;
            ls0 += __shfl_xor_sync(0xffffffffu, ls0, 1);
            ls0 += __shfl_xor_sync(0xffffffffu, ls0, 2);
            ls1 += __shfl_xor_sync(0xffffffffu, ls1, 1);
            ls1 += __shfl_xor_sync(0xffffffffu, ls1, 2);
            l0 = l0 * c0 + ls0;
            l1 = l1 * c1 + ls1;
            unsigned pa[4];
            pa[0] = packbf(p00, p01);
            pa[1] = packbf(p10, p11);
            pa[2] = packbf(p02, p03);
            pa[3] = packbf(p12, p13);
            #pragma unroll
            for (int j = 0; j < 8; j++) {
                oa[j][0] *= c0; oa[j][1] *= c0;
                oa[j][2] *= c1; oa[j][3] *= c1;
            }
            #pragma unroll
            for (int dg = 0; dg < 4; dg++) {
                unsigned vr[4];
                ldsm4t(vr, sptr(&Vs[buf][frow * ATS + dg * 16 + fch]));
                unsigned vb0[2] = {vr[0], vr[1]}, vb1[2] = {vr[2], vr[3]};
                mma_bf16(oa[2 * dg],     pa, vb0);
                mma_bf16(oa[2 * dg + 1], pa, vb1);
            }
        }
        __syncthreads();
    }

    float inv0 = 1.f / l0, inv1 = 1.f / l1;
    size_t ob0 = (size_t)(b * SEQ + qb * 16 + g) * DIM + h * HD;
    size_t ob1 = (size_t)(b * SEQ + qb * 16 + g + 8) * DIM + h * HD;
    #pragma unroll
    for (int j = 0; j < 8; j++) {
        int col = j * 8 + 2 * tg;
        *(__nv_bfloat162*)&g_o[ob0 + col] =
            __floats2bfloat162_rn(oa[j][0] * inv0, oa[j][1] * inv0);
        *(__nv_bfloat162*)&g_o[ob1 + col] =
            __floats2bfloat162_rn(oa[j][2] * inv1, oa[j][3] * inv1);
    }
}

// ---------------- launch ----------------
extern "C" void kernel_launch(void* const* d_in, const int* in_sizes, int n_in,
                              void* d_out, int out_size) {
    const float* x     = (const float*)d_in[0];
    const float* cosb  = (const float*)d_in[1];
    const float* sinb  = (const float*)d_in[2];
    const float* c     = (const float*)d_in[3];
    const float* W_qkv = (const float*)d_in[4];
    const float* W_out = (const float*)d_in[5];
    const float* ln1_w = (const float*)d_in[6];
    const float* ln2_w = (const float*)d_in[7];
    const float* w1    = (const float*)d_in[8];
    const float* b1    = (const float*)d_in[9];
    const float* w2    = (const float*)d_in[10];
    const float* b2    = (const float*)d_in[11];
    const float* ada_w = (const float*)d_in[12];
    const float* ada_b = (const float*)d_in[13];
    float* out = (float*)d_out;

    bf16 *h, *o, *h2, *mlp, *wq, *wo, *w1b, *w2b, *qkv;
    float *x1;
    cudaGetSymbolAddress((void**)&h,   g_h);
    cudaGetSymbolAddress((void**)&qkv, g_qkv);
    cudaGetSymbolAddress((void**)&o,   g_o);
    cudaGetSymbolAddress((void**)&x1,  g_x1);
    cudaGetSymbolAddress((void**)&h2,  g_h2);
    cudaGetSymbolAddress((void**)&mlp, g_mlp);
    cudaGetSymbolAddress((void**)&wq,  g_wq);
    cudaGetSymbolAddress((void**)&wo,  g_wo);
    cudaGetSymbolAddress((void**)&w1b, g_w1);
    cudaGetSymbolAddress((void**)&w2b, g_w2);

    cudaFuncSetAttribute((const void*)gemm_bf16<4, 128, 3>,
                         cudaFuncAttributeMaxDynamicSharedMemorySize, SMEM_G128_3);
    cudaFuncSetAttribute((const void*)gemm_bf16<2, 128, 3>,
                         cudaFuncAttributeMaxDynamicSharedMemorySize, SMEM_G128_3);
    cudaFuncSetAttribute((const void*)gemm_bf16<1, 64, 2>,
                         cudaFuncAttributeMaxDynamicSharedMemorySize, SMEM_G64);
    cudaFuncSetAttribute((const void*)gemm_bf16<3, 64, 2>,
                         cudaFuncAttributeMaxDynamicSharedMemorySize, SMEM_G64);

    const int M = BB * SEQ;  // 4096

    cvt_all_kernel<<<1184, 512>>>((const float4*)W_qkv, (const float4*)W_out,
                                  (const float4*)w1, (const float4*)w2);

    ada_kernel<<<(BB * ADA6 + 255) / 256, 256>>>(c, ada_w, ada_b);
    ln_mod_kernel<<<M, 256>>>(x, h, ln1_w, 0, DIM);
    // QKV -> bf16 qkv (TN=128, 3-stage)
    gemm_bf16<4, 128, 3><<<dim3(3 * DIM / 128, M / 128), 256, SMEM_G128_3>>>(
        h, wq, qkv, 3 * DIM, DIM, nullptr, nullptr, 0);
    {
        int total = BB * SEQ * 3 * HEADS * 32;
        rope_kernel<<<(total + 255) / 256, 256>>>(cosb, sinb);
    }
    attn_mma<<<dim3(32, HEADS, BB), 128>>>();
    // out-proj + gate_msa + residual(x)  (TN=64, 2-stage)
    gemm_bf16<1, 64, 2><<<dim3(DIM / 64, M / 128), 256, SMEM_G64>>>(
        o, wo, x1, DIM, DIM, nullptr, x, 2 * DIM);
    ln_mod_kernel<<<M, 256>>>(x1, h2, ln2_w, 3 * DIM, 4 * DIM);
    // MLP1 + bias + gelu (TN=128, 3-stage)
    gemm_bf16<2, 128, 3><<<dim3(DFF / 128, M / 128), 256, SMEM_G128_3>>>(
        h2, w1b, mlp, DFF, DIM, b1, nullptr, 0);
    // MLP2 + bias + gate_mlp + residual(x1)  (TN=64, 2-stage)
    gemm_bf16<3, 64, 2><<<dim3(DIM / 64, M / 128), 256, SMEM_G64>>>(
        mlp, w2b, out, DIM, DFF, b2, x1, 5 * DIM);
}

// round 17
// speedup vs baseline: 1.0832x; 1.0832x over previous
#include <cuda_runtime.h>
#include <cuda_bf16.h>
#include <cstdint>

#define BB 2
#define SEQ 2048
#define NHALF 1024
#define DIM 768
#define HEADS 12
#define HD 64
#define DFF 3072
#define COND 128
#define ADA6 (6 * DIM)

typedef __nv_bfloat16 bf16;

// ---------------- scratch ----------------
__device__ float g_ada[BB * ADA6];
__device__ bf16  g_h  [BB * SEQ * DIM];
__device__ bf16  g_qkv[BB * SEQ * 3 * DIM];
__device__ bf16  g_o  [BB * SEQ * DIM];
__device__ float g_x1 [BB * SEQ * DIM];
__device__ bf16  g_h2 [BB * SEQ * DIM];
__device__ bf16  g_mlp[BB * SEQ * DFF];
// bf16 weight copies [K][N]
__device__ bf16 g_wq[DIM * 3 * DIM];
__device__ bf16 g_wo[DIM * DIM];
__device__ bf16 g_w1[DIM * DFF];
__device__ bf16 g_w2[DFF * DIM];

// ---------------- helpers ----------------
__device__ __forceinline__ unsigned sptr(const void* p) {
    return (unsigned)__cvta_generic_to_shared(p);
}
__device__ __forceinline__ void cpa16(unsigned dst, const void* src) {
    asm volatile("cp.async.cg.shared.global [%0], [%1], 16;" :: "r"(dst), "l"(src));
}
__device__ __forceinline__ void ldsm4(unsigned* r, unsigned addr) {
    asm volatile("ldmatrix.sync.aligned.m8n8.x4.shared.b16 {%0,%1,%2,%3}, [%4];"
                 : "=r"(r[0]), "=r"(r[1]), "=r"(r[2]), "=r"(r[3]) : "r"(addr));
}
__device__ __forceinline__ void ldsm4t(unsigned* r, unsigned addr) {
    asm volatile("ldmatrix.sync.aligned.m8n8.x4.trans.shared.b16 {%0,%1,%2,%3}, [%4];"
                 : "=r"(r[0]), "=r"(r[1]), "=r"(r[2]), "=r"(r[3]) : "r"(addr));
}
__device__ __forceinline__ void mma_bf16(float* c, const unsigned* a, const unsigned* b) {
    asm volatile(
        "mma.sync.aligned.m16n8k16.row.col.f32.bf16.bf16.f32 "
        "{%0,%1,%2,%3}, {%4,%5,%6,%7}, {%8,%9}, {%0,%1,%2,%3};"
        : "+f"(c[0]), "+f"(c[1]), "+f"(c[2]), "+f"(c[3])
        : "r"(a[0]), "r"(a[1]), "r"(a[2]), "r"(a[3]), "r"(b[0]), "r"(b[1]));
}
__device__ __forceinline__ unsigned packbf(float a, float b) {
    __nv_bfloat162 p = __floats2bfloat162_rn(a, b);
    return *(unsigned*)&p;
}
__device__ __forceinline__ float tanh_fast(float x) {
    float y;
    asm("tanh.approx.f32 %0, %1;" : "=f"(y) : "f"(x));
    return y;
}
__device__ __forceinline__ float gelu_tanh(float v) {
    float t = v * v * v;
    return 0.5f * v * (1.f + tanh_fast(0.7978845608028654f * (v + 0.044715f * t)));
}

// ---------------- fused weight convert (all 4 weights, one launch) ----------------
#define NQ_WQ (DIM * 3 * DIM / 4)
#define NQ_WO (DIM * DIM / 4)
#define NQ_W1 (DIM * DFF / 4)
#define NQ_W2 (DFF * DIM / 4)
#define NQ_ALL (NQ_WQ + NQ_WO + NQ_W1 + NQ_W2)

__global__ void cvt_all_kernel(const float4* __restrict__ s0, const float4* __restrict__ s1,
                               const float4* __restrict__ s2, const float4* __restrict__ s3) {
    int i = blockIdx.x * blockDim.x + threadIdx.x;
    int stride = gridDim.x * blockDim.x;
    for (; i < NQ_ALL; i += stride) {
        const float4* src;
        uint2* dst;
        int j = i;
        if (j < NQ_WQ) { src = s0; dst = (uint2*)g_wq; }
        else if ((j -= NQ_WQ) < NQ_WO) { src = s1; dst = (uint2*)g_wo; }
        else if ((j -= NQ_WO) < NQ_W1) { src = s2; dst = (uint2*)g_w1; }
        else { j -= NQ_W1; src = s3; dst = (uint2*)g_w2; }
        float4 v = src[j];
        uint2 o;
        o.x = packbf(v.x, v.y);
        o.y = packbf(v.z, v.w);
        dst[j] = o;
    }
}

// ---------------- ada = c @ ada_w + ada_b ----------------
__global__ void ada_kernel(const float* __restrict__ c,
                           const float* __restrict__ ada_w,
                           const float* __restrict__ ada_b) {
    int j = blockIdx.x * blockDim.x + threadIdx.x;
    if (j >= BB * ADA6) return;
    int b = j / ADA6, col = j % ADA6;
    float acc = ada_b[col];
    #pragma unroll 8
    for (int k = 0; k < COND; k++)
        acc += c[b * COND + k] * ada_w[k * ADA6 + col];
    g_ada[j] = acc;
}

// ---------------- LayerNorm + adaLN modulation (bf16 out) ----------------
__global__ void ln_mod_kernel(const float* __restrict__ src, bf16* __restrict__ dst,
                              const float* __restrict__ lnw,
                              int shift_ofs, int scale_ofs) {
    int row = blockIdx.x;
    int b = row / SEQ;
    const float* xr = src + (size_t)row * DIM;
    float s = 0.f, s2 = 0.f;
    for (int i = threadIdx.x; i < DIM; i += blockDim.x) {
        float v = xr[i];
        s += v; s2 += v * v;
    }
    #pragma unroll
    for (int o = 16; o; o >>= 1) {
        s  += __shfl_xor_sync(0xffffffffu, s,  o);
        s2 += __shfl_xor_sync(0xffffffffu, s2, o);
    }
    __shared__ float red[64];
    int wid = threadIdx.x >> 5, lid = threadIdx.x & 31;
    if (lid == 0) { red[wid] = s; red[32 + wid] = s2; }
    __syncthreads();
    if (threadIdx.x == 0) {
        float a = 0.f, bs = 0.f;
        int nw = blockDim.x >> 5;
        for (int w = 0; w < nw; w++) { a += red[w]; bs += red[32 + w]; }
        red[0] = a; red[32] = bs;
    }
    __syncthreads();
    float mu  = red[0] * (1.0f / DIM);
    float var = red[32] * (1.0f / DIM) - mu * mu;
    float inv = rsqrtf(var + 1e-5f);
    const float* ada = g_ada + b * ADA6;
    for (int i = threadIdx.x; i < DIM; i += blockDim.x) {
        float v = (xr[i] - mu) * inv * lnw[i];
        dst[(size_t)row * DIM + i] =
            __float2bfloat16(v * (1.f + ada[scale_ofs + i]) + ada[shift_ofs + i]);
    }
}

// ---------------- bf16 mma.sync GEMM (R15 frozen config) ----------------
// MODE 1: gate*acc+res (fp32) | 2: gelu(acc+bias)->bf16 | 3: gate*(acc+bias)+res (fp32)
// MODE 4: bf16 raw out.   TN = CTA tile N-width (128 or 64).
#define A64ST 72                     // A smem row stride (bf16): 144B, conflict-free
#define STG_A (128 * A64ST)          // 9216 elems

template <int MODE, int TN>
__global__ void __launch_bounds__(256)
gemm_bf16(const bf16* __restrict__ A, const bf16* __restrict__ Bm,
          void* __restrict__ Cv, int N, int K,
          const float* __restrict__ bias,
          const float* __restrict__ res, int gate_ofs) {
    constexpr int NT = TN / 16;
    constexpr int NP = TN / 32;
    constexpr int BITER = TN / 32;
    constexpr int BCH = TN / 8;
    constexpr int STG_Bv = 64 * TN;
    constexpr int STG_Tv = STG_A + STG_Bv;

    extern __shared__ bf16 smem[];
    int tid = threadIdx.x;
    int lane = tid & 31, warp = tid >> 5;
    int warpm = warp >> 1, warpn = warp & 1;
    int g = lane >> 2, tg = lane & 3;
    int m0 = blockIdx.y * 128, n0 = blockIdx.x * TN;

    float acc[2][NT][4] = {};

    int T = K / 64;

    #define LOAD_STAGE64(it, st) do { \
        bf16* sa = smem + (st) * STG_Tv; \
        bf16* sb = sa + STG_A; \
        int kofs = (it) * 64; \
        _Pragma("unroll") \
        for (int i4 = 0; i4 < 4; i4++) { \
            int e = tid + i4 * 256; \
            int row = e >> 3, c = e & 7; \
            cpa16(sptr(sa + row * A64ST + c * 8), \
                  &A[(size_t)(m0 + row) * K + kofs + c * 8]); \
        } \
        _Pragma("unroll") \
        for (int i4 = 0; i4 < BITER; i4++) { \
            int e = tid + i4 * 256; \
            int k = e / BCH, bc2 = e % BCH; \
            cpa16(sptr(sb + k * TN + ((bc2 ^ (k & 7)) * 8)), \
                  &Bm[(size_t)(kofs + k) * N + n0 + bc2 * 8]); \
        } \
        asm volatile("cp.async.commit_group;"); \
    } while (0)

    LOAD_STAGE64(0, 0);
    if (T > 1) LOAD_STAGE64(1, 1);

    for (int it = 0; it < T; it++) {
        int buf = it & 1;
        if (it + 1 < T) asm volatile("cp.async.wait_group 1;");
        else            asm volatile("cp.async.wait_group 0;");
        __syncthreads();

        const bf16* sa = smem + buf * STG_Tv;
        const bf16* sb = sa + STG_A;

        #pragma unroll
        for (int s = 0; s < 4; s++) {
            unsigned a[2][4], b[NT][2];
            #pragma unroll
            for (int mt = 0; mt < 2; mt++) {
                int row = warpm * 32 + mt * 16 + (lane & 15);
                ldsm4(a[mt], sptr(sa + row * A64ST + s * 16 + (lane >> 4) * 8));
            }
            #pragma unroll
            for (int p = 0; p < NP; p++) {
                int k = s * 16 + (lane & 7) + ((lane >> 3) & 1) * 8;
                int nn = warpn * (TN / 2) + p * 16 + (lane >> 4) * 8;
                unsigned r[4];
                ldsm4t(r, sptr(sb + k * TN + (((nn >> 3) ^ (k & 7)) * 8)));
                b[2 * p][0] = r[0]; b[2 * p][1] = r[1];
                b[2 * p + 1][0] = r[2]; b[2 * p + 1][1] = r[3];
            }
            #pragma unroll
            for (int mt = 0; mt < 2; mt++)
                #pragma unroll
                for (int nt = 0; nt < NT; nt++)
                    mma_bf16(acc[mt][nt], a[mt], b[nt]);
        }
        __syncthreads();
        if (it + 2 < T) LOAD_STAGE64(it + 2, buf);
    }

    float* C = (float*)Cv;
    bf16* Cb = (bf16*)Cv;
    #pragma unroll
    for (int mt = 0; mt < 2; mt++) {
        #pragma unroll
        for (int i = 0; i < 2; i++) {
            int row = m0 + warpm * 32 + mt * 16 + g + i * 8;
            int bidx = row >> 11;
            #pragma unroll
            for (int nt = 0; nt < NT; nt++) {
                int col = n0 + warpn * (TN / 2) + nt * 8 + 2 * tg;
                float v0 = acc[mt][nt][i * 2 + 0];
                float v1 = acc[mt][nt][i * 2 + 1];
                if (MODE == 4) {
                    *(__nv_bfloat162*)&Cb[(size_t)row * N + col] = __floats2bfloat162_rn(v0, v1);
                } else if (MODE == 1) {
                    float g0 = g_ada[bidx * ADA6 + gate_ofs + col];
                    float g1 = g_ada[bidx * ADA6 + gate_ofs + col + 1];
                    v0 = g0 * v0 + res[(size_t)row * N + col];
                    v1 = g1 * v1 + res[(size_t)row * N + col + 1];
                    *(float2*)&C[(size_t)row * N + col] = make_float2(v0, v1);
                } else if (MODE == 2) {
                    v0 = gelu_tanh(v0 + bias[col]);
                    v1 = gelu_tanh(v1 + bias[col + 1]);
                    *(__nv_bfloat162*)&Cb[(size_t)row * N + col] = __floats2bfloat162_rn(v0, v1);
                } else if (MODE == 3) {
                    v0 += bias[col]; v1 += bias[col + 1];
                    float g0 = g_ada[bidx * ADA6 + gate_ofs + col];
                    float g1 = g_ada[bidx * ADA6 + gate_ofs + col + 1];
                    v0 = g0 * v0 + res[(size_t)row * N + col];
                    v1 = g1 * v1 + res[(size_t)row * N + col + 1];
                    *(float2*)&C[(size_t)row * N + col] = make_float2(v0, v1);
                }
            }
        }
    }
}

#define SMEM_G128 (2 * (STG_A + 64 * 128) * 2)
#define SMEM_G64  (2 * (STG_A + 64 * 64) * 2)

// ---------------- RoPE on bf16 qkv ----------------
__global__ void rope_kernel(const float* __restrict__ cosb, const float* __restrict__ sinb) {
    int idx = blockIdx.x * blockDim.x + threadIdx.x;
    const int total = BB * SEQ * 3 * HEADS * 32;
    if (idx >= total) return;
    int d = idx & 31;
    int h = (idx >> 5) % HEADS;
    int t = (idx / (32 * HEADS)) % 3;
    int pos = (idx / (32 * HEADS * 3)) % SEQ;
    int b = idx / (32 * HEADS * 3 * SEQ);
    int ph = pos & (NHALF - 1);
    float c1 = cosb[ph * HD + d],      s1 = sinb[ph * HD + d];
    float c2 = cosb[ph * HD + d + 32], s2 = sinb[ph * HD + d + 32];
    bf16* base = g_qkv + ((size_t)(b * SEQ + pos) * 3 + t) * DIM + h * HD;
    float v1 = __bfloat162float(base[d]), v2 = __bfloat162float(base[d + 32]);
    base[d]      = __float2bfloat16(v1 * c1 - v2 * s1);
    base[d + 32] = __float2bfloat16(v2 * c2 + v1 * s2);
}

// ---------------- mma flash attention, block-sparse, 4-buffer ring, 1 sync/iter ----------------
#define ATS 72   // smem row stride elems (144B): conflict-free ldsm

__global__ void __launch_bounds__(128) attn_mma() {
    __shared__ bf16 Qs[64 * ATS];
    __shared__ bf16 Ks[4][16 * ATS];
    __shared__ bf16 Vs[4][16 * ATS];
    int tid = threadIdx.x, w = tid >> 5, lane = tid & 31;
    int bx = blockIdx.x, h = blockIdx.y, b = blockIdx.z;
    int qb0 = (bx & 1) ? (60 - 4 * (bx >> 1)) : (124 - 4 * (bx >> 1));
    bool first = qb0 < 64;
    int qb = qb0 + w;
    int g = lane >> 2, tg = lane & 3;
    int frow = lane & 15, fch = (lane >> 4) * 8;

    {
        const bf16* qsrc = g_qkv + ((size_t)(b * SEQ + qb0 * 16) * 3) * DIM + h * HD;
        #pragma unroll
        for (int i = 0; i < 4; i++) {
            int e = tid + i * 128;
            int row = e >> 3, c = e & 7;
            *(uint4*)&Qs[row * ATS + c * 8] =
                *(const uint4*)&qsrc[(size_t)row * 3 * DIM + c * 8];
        }
    }
    __syncthreads();

    unsigned qa[4][4];
    #pragma unroll
    for (int s = 0; s < 4; s++)
        ldsm4(qa[s], sptr(&Qs[(w * 16 + frow) * ATS + s * 16 + fch]));

    int nit = first ? (qb0 + 7) : (qb0 - 60);
    #define KB(i) (first ? ((i) < 4 ? qb0 + (i) : 60 + (i)) : 64 + (i))

    #define ATT_LOAD(kb, bf) do { \
        int row = tid >> 3, c = tid & 7; \
        const bf16* kv = g_qkv + ((size_t)(b * SEQ + (kb) * 16 + row) * 3 + 1) * DIM \
                         + h * HD + c * 8; \
        cpa16(sptr(&Ks[bf][row * ATS + c * 8]), kv); \
        cpa16(sptr(&Vs[bf][row * ATS + c * 8]), kv + DIM); \
        asm volatile("cp.async.commit_group;"); \
    } while (0)

    float m0v = -1e30f, m1v = -1e30f, l0 = 0.f, l1 = 0.f;
    float oa[8][4] = {};

    ATT_LOAD(KB(0), 0);
    for (int it = 0; it < nit; it++) {
        int buf = it & 3;
        // issue load for it+1 into (it+1)&3 — cannot collide: other warps are at
        // most computing it-1 (buffer (it-1)&3) and (it+1)&3 was last read at it-3,
        // which all warps finished before this iteration's barrier.
        if (it + 1 < nit) {
            ATT_LOAD(KB(it + 1), (it + 1) & 3);
            asm volatile("cp.async.wait_group 1;");
        } else {
            asm volatile("cp.async.wait_group 0;");
        }
        __syncthreads();        // single barrier per iteration

        bool act = first ? ((it < 4) ? (it == w) : (it - 4 < qb0 + w))
                         : (it < qb0 - 64 + w + 1);
        if (act) {
            float s0[4] = {0, 0, 0, 0}, s1[4] = {0, 0, 0, 0};
            #pragma unroll
            for (int s = 0; s < 4; s++) {
                unsigned kr[4];
                ldsm4(kr, sptr(&Ks[buf][frow * ATS + s * 16 + fch]));
                unsigned b0[2] = {kr[0], kr[2]}, b1[2] = {kr[1], kr[3]};
                mma_bf16(s0, qa[s], b0);
                mma_bf16(s1, qa[s], b1);
            }
            #pragma unroll
            for (int q = 0; q < 4; q++) { s0[q] *= 0.125f; s1[q] *= 0.125f; }
            float rm0 = fmaxf(fmaxf(s0[0], s0[1]), fmaxf(s1[0], s1[1]));
            float rm1 = fmaxf(fmaxf(s0[2], s0[3]), fmaxf(s1[2], s1[3]));
            rm0 = fmaxf(rm0, __shfl_xor_sync(0xffffffffu, rm0, 1));
            rm0 = fmaxf(rm0, __shfl_xor_sync(0xffffffffu, rm0, 2));
            rm1 = fmaxf(rm1, __shfl_xor_sync(0xffffffffu, rm1, 1));
            rm1 = fmaxf(rm1, __shfl_xor_sync(0xffffffffu, rm1, 2));
            float nm0 = fmaxf(m0v, rm0), nm1 = fmaxf(m1v, rm1);
            float c0 = __expf(m0v - nm0), c1 = __expf(m1v - nm1);
            m0v = nm0; m1v = nm1;
            float p00 = __expf(s0[0] - nm0), p01 = __expf(s0[1] - nm0);
            float p02 = __expf(s1[0] - nm0), p03 = __expf(s1[1] - nm0);
            float p10 = __expf(s0[2] - nm1), p11 = __expf(s0[3] - nm1);
            float p12 = __expf(s1[2] - nm1), p13 = __expf(s1[3] - nm1);
            float ls0 = p00 + p01 + p02 + p03;
            float ls1 = p10 + p11 + p12 + p13;
            ls0 += __shfl_xor_sync(0xffffffffu, ls0, 1);
            ls0 += __shfl_xor_sync(0xffffffffu, ls0, 2);
            ls1 += __shfl_xor_sync(0xffffffffu, ls1, 1);
            ls1 += __shfl_xor_sync(0xffffffffu, ls1, 2);
            l0 = l0 * c0 + ls0;
            l1 = l1 * c1 + ls1;
            unsigned pa[4];
            pa[0] = packbf(p00, p01);
            pa[1] = packbf(p10, p11);
            pa[2] = packbf(p02, p03);
            pa[3] = packbf(p12, p13);
            #pragma unroll
            for (int j = 0; j < 8; j++) {
                oa[j][0] *= c0; oa[j][1] *= c0;
                oa[j][2] *= c1; oa[j][3] *= c1;
            }
            #pragma unroll
            for (int dg = 0; dg < 4; dg++) {
                unsigned vr[4];
                ldsm4t(vr, sptr(&Vs[buf][frow * ATS + dg * 16 + fch]));
                unsigned vb0[2] = {vr[0], vr[1]}, vb1[2] = {vr[2], vr[3]};
                mma_bf16(oa[2 * dg],     pa, vb0);
                mma_bf16(oa[2 * dg + 1], pa, vb1);
            }
        }
    }

    float inv0 = 1.f / l0, inv1 = 1.f / l1;
    size_t ob0 = (size_t)(b * SEQ + qb * 16 + g) * DIM + h * HD;
    size_t ob1 = (size_t)(b * SEQ + qb * 16 + g + 8) * DIM + h * HD;
    #pragma unroll
    for (int j = 0; j < 8; j++) {
        int col = j * 8 + 2 * tg;
        *(__nv_bfloat162*)&g_o[ob0 + col] =
            __floats2bfloat162_rn(oa[j][0] * inv0, oa[j][1] * inv0);
        *(__nv_bfloat162*)&g_o[ob1 + col] =
            __floats2bfloat162_rn(oa[j][2] * inv1, oa[j][3] * inv1);
    }
}

// ---------------- launch ----------------
extern "C" void kernel_launch(void* const* d_in, const int* in_sizes, int n_in,
                              void* d_out, int out_size) {
    const float* x     = (const float*)d_in[0];
    const float* cosb  = (const float*)d_in[1];
    const float* sinb  = (const float*)d_in[2];
    const float* c     = (const float*)d_in[3];
    const float* W_qkv = (const float*)d_in[4];
    const float* W_out = (const float*)d_in[5];
    const float* ln1_w = (const float*)d_in[6];
    const float* ln2_w = (const float*)d_in[7];
    const float* w1    = (const float*)d_in[8];
    const float* b1    = (const float*)d_in[9];
    const float* w2    = (const float*)d_in[10];
    const float* b2    = (const float*)d_in[11];
    const float* ada_w = (const float*)d_in[12];
    const float* ada_b = (const float*)d_in[13];
    float* out = (float*)d_out;

    bf16 *h, *o, *h2, *mlp, *wq, *wo, *w1b, *w2b, *qkv;
    float *x1;
    cudaGetSymbolAddress((void**)&h,   g_h);
    cudaGetSymbolAddress((void**)&qkv, g_qkv);
    cudaGetSymbolAddress((void**)&o,   g_o);
    cudaGetSymbolAddress((void**)&x1,  g_x1);
    cudaGetSymbolAddress((void**)&h2,  g_h2);
    cudaGetSymbolAddress((void**)&mlp, g_mlp);
    cudaGetSymbolAddress((void**)&wq,  g_wq);
    cudaGetSymbolAddress((void**)&wo,  g_wo);
    cudaGetSymbolAddress((void**)&w1b, g_w1);
    cudaGetSymbolAddress((void**)&w2b, g_w2);

    cudaFuncSetAttribute((const void*)gemm_bf16<4, 128>,
                         cudaFuncAttributeMaxDynamicSharedMemorySize, SMEM_G128);
    cudaFuncSetAttribute((const void*)gemm_bf16<2, 128>,
                         cudaFuncAttributeMaxDynamicSharedMemorySize, SMEM_G128);
    cudaFuncSetAttribute((const void*)gemm_bf16<1, 64>,
                         cudaFuncAttributeMaxDynamicSharedMemorySize, SMEM_G64);
    cudaFuncSetAttribute((const void*)gemm_bf16<3, 64>,
                         cudaFuncAttributeMaxDynamicSharedMemorySize, SMEM_G64);

    const int M = BB * SEQ;  // 4096

    cvt_all_kernel<<<1184, 512>>>((const float4*)W_qkv, (const float4*)W_out,
                                  (const float4*)w1, (const float4*)w2);

    ada_kernel<<<(BB * ADA6 + 255) / 256, 256>>>(c, ada_w, ada_b);
    ln_mod_kernel<<<M, 256>>>(x, h, ln1_w, 0, DIM);
    // QKV -> bf16 qkv (TN=128)
    gemm_bf16<4, 128><<<dim3(3 * DIM / 128, M / 128), 256, SMEM_G128>>>(
        h, wq, qkv, 3 * DIM, DIM, nullptr, nullptr, 0);
    {
        int total = BB * SEQ * 3 * HEADS * 32;
        rope_kernel<<<(total + 255) / 256, 256>>>(cosb, sinb);
    }
    attn_mma<<<dim3(32, HEADS, BB), 128>>>();
    // out-proj + gate_msa + residual(x)  (TN=64)
    gemm_bf16<1, 64><<<dim3(DIM / 64, M / 128), 256, SMEM_G64>>>(
        o, wo, x1, DIM, DIM, nullptr, x, 2 * DIM);
    ln_mod_kernel<<<M, 256>>>(x1, h2, ln2_w, 3 * DIM, 4 * DIM);
    // MLP1 + bias + gelu (TN=128)
    gemm_bf16<2, 128><<<dim3(DFF / 128, M / 128), 256, SMEM_G128>>>(
        h2, w1b, mlp, DFF, DIM, b1, nullptr, 0);
    // MLP2 + bias + gate_mlp + residual(x1)  (TN=64)
    gemm_bf16<3, 64><<<dim3(DIM / 64, M / 128), 256, SMEM_G64>>>(
        mlp, w2b, out, DIM, DFF, b2, x1, 5 * DIM);
}